// round 9
// baseline (speedup 1.0000x reference)
#include <cuda_runtime.h>
#include <cuda_fp16.h>
#include <cstdint>

#define TT 1024
#define BB 32
#define HD 512
#define NG 1536           // 3*HD
#define MM (TT*BB)        // 32768

typedef unsigned long long ull;

// ---------------- device scratch (no allocations allowed) ----------------
__device__ float g_gi0[(size_t)MM * NG];     // forward gi
__device__ float g_gi1[(size_t)MM * NG];     // backward gi
__device__ float g_buf0[(size_t)MM * 1024];  // layer0 output
__device__ float g_buf1[(size_t)MM * 1024];  // layer1 output
__device__ __half g_h16[2][2][BB * HD];      // ping-pong h per direction (fp16 exchange)
__device__ __align__(128) unsigned g_flag[4][32];  // per-group per-CTA step flags

// ========================= common helpers =========================
__device__ __forceinline__ unsigned pack2(float a, float b) {
    __half2 h = __floats2half2_rn(a, b);
    return *(unsigned*)&h;
}
__device__ __forceinline__ void mma16(float* d, const unsigned* a, const unsigned* b) {
    asm volatile("mma.sync.aligned.m16n8k16.row.col.f32.f16.f16.f32 "
                 "{%0,%1,%2,%3}, {%4,%5,%6,%7}, {%8,%9}, {%0,%1,%2,%3};"
                 : "+f"(d[0]), "+f"(d[1]), "+f"(d[2]), "+f"(d[3])
                 : "r"(a[0]), "r"(a[1]), "r"(a[2]), "r"(a[3]), "r"(b[0]), "r"(b[1]));
}
__device__ __forceinline__ float sigm(float x) { return 1.f / (1.f + __expf(-x)); }

// ========================= fp16 mma.sync projection GEMM =========================
#define BM 128
#define BN 128
#define BK 32
#define SSH 40

__global__ __launch_bounds__(256, 2) void gemm_tc(
    const float* __restrict__ A,
    const float* __restrict__ W0, const float* __restrict__ W1,
    const float* __restrict__ bi0, const float* __restrict__ bi1,
    float* __restrict__ C0, float* __restrict__ C1, int K)
{
    __shared__ __half sAB[2][2][128 * SSH];
    __shared__ float sbias[BN];

    int tid = threadIdx.x, warp = tid >> 5, lane = tid & 31;
    int g = lane >> 2, t = lane & 3;
    int wm = (warp & 3) * 32;
    int wn = (warp >> 2) * 64;

    int n0 = blockIdx.x * BN;
    int m0 = blockIdx.y * BM;
    int dz = blockIdx.z;
    const float* W    = dz ? W1  : W0;
    const float* bias = dz ? bi1 : bi0;
    float*       C    = dz ? C1  : C0;

    if (tid < BN) sbias[tid] = bias[n0 + tid];

    int grow = tid >> 1, gcol = (tid & 1) * 16;
    const float* Ag = A + (size_t)(m0 + grow) * K + gcol;
    const float* Wg = W + (size_t)(n0 + grow) * K + gcol;

    float acc[2][8][4];
#pragma unroll
    for (int mt = 0; mt < 2; mt++)
#pragma unroll
        for (int nt = 0; nt < 8; nt++)
#pragma unroll
            for (int e = 0; e < 4; e++) acc[mt][nt][e] = 0.f;

    int kT = K / BK;
    float4 av[4], wv[4];

#pragma unroll
    for (int q = 0; q < 4; q++) { av[q] = *(const float4*)(Ag + q * 4); wv[q] = *(const float4*)(Wg + q * 4); }
    {
        uint4 ua0 = { pack2(av[0].x, av[0].y), pack2(av[0].z, av[0].w), pack2(av[1].x, av[1].y), pack2(av[1].z, av[1].w) };
        uint4 ua1 = { pack2(av[2].x, av[2].y), pack2(av[2].z, av[2].w), pack2(av[3].x, av[3].y), pack2(av[3].z, av[3].w) };
        uint4 uw0 = { pack2(wv[0].x, wv[0].y), pack2(wv[0].z, wv[0].w), pack2(wv[1].x, wv[1].y), pack2(wv[1].z, wv[1].w) };
        uint4 uw1 = { pack2(wv[2].x, wv[2].y), pack2(wv[2].z, wv[2].w), pack2(wv[3].x, wv[3].y), pack2(wv[3].z, wv[3].w) };
        *(uint4*)&sAB[0][0][grow * SSH + gcol]     = ua0;
        *(uint4*)&sAB[0][0][grow * SSH + gcol + 8] = ua1;
        *(uint4*)&sAB[0][1][grow * SSH + gcol]     = uw0;
        *(uint4*)&sAB[0][1][grow * SSH + gcol + 8] = uw1;
    }
    __syncthreads();

    for (int s = 0; s < kT; s++) {
        int bb = s & 1;
        if (s + 1 < kT) {
            int k0 = (s + 1) * BK;
#pragma unroll
            for (int q = 0; q < 4; q++) {
                av[q] = *(const float4*)(Ag + k0 + q * 4);
                wv[q] = *(const float4*)(Wg + k0 + q * 4);
            }
        }
        const __half* a_s = sAB[bb][0];
        const __half* b_s = sAB[bb][1];
#pragma unroll
        for (int kk = 0; kk < 2; kk++) {
            int k0 = kk * 16;
            unsigned afr[2][4], bfr[8][2];
#pragma unroll
            for (int mt = 0; mt < 2; mt++) {
                int base = (wm + mt * 16 + g) * SSH + k0 + 2 * t;
                afr[mt][0] = *(const unsigned*)&a_s[base];
                afr[mt][1] = *(const unsigned*)&a_s[base + 8 * SSH];
                afr[mt][2] = *(const unsigned*)&a_s[base + 8];
                afr[mt][3] = *(const unsigned*)&a_s[base + 8 * SSH + 8];
            }
#pragma unroll
            for (int nt = 0; nt < 8; nt++) {
                int base = (wn + nt * 8 + g) * SSH + k0 + 2 * t;
                bfr[nt][0] = *(const unsigned*)&b_s[base];
                bfr[nt][1] = *(const unsigned*)&b_s[base + 8];
            }
#pragma unroll
            for (int mt = 0; mt < 2; mt++)
#pragma unroll
                for (int nt = 0; nt < 8; nt++)
                    mma16(acc[mt][nt], afr[mt], bfr[nt]);
        }
        if (s + 1 < kT) {
            uint4 ua0 = { pack2(av[0].x, av[0].y), pack2(av[0].z, av[0].w), pack2(av[1].x, av[1].y), pack2(av[1].z, av[1].w) };
            uint4 ua1 = { pack2(av[2].x, av[2].y), pack2(av[2].z, av[2].w), pack2(av[3].x, av[3].y), pack2(av[3].z, av[3].w) };
            uint4 uw0 = { pack2(wv[0].x, wv[0].y), pack2(wv[0].z, wv[0].w), pack2(wv[1].x, wv[1].y), pack2(wv[1].z, wv[1].w) };
            uint4 uw1 = { pack2(wv[2].x, wv[2].y), pack2(wv[2].z, wv[2].w), pack2(wv[3].x, wv[3].y), pack2(wv[3].z, wv[3].w) };
            int nb = bb ^ 1;
            *(uint4*)&sAB[nb][0][grow * SSH + gcol]     = ua0;
            *(uint4*)&sAB[nb][0][grow * SSH + gcol + 8] = ua1;
            *(uint4*)&sAB[nb][1][grow * SSH + gcol]     = uw0;
            *(uint4*)&sAB[nb][1][grow * SSH + gcol + 8] = uw1;
        }
        __syncthreads();
    }

#pragma unroll
    for (int mt = 0; mt < 2; mt++) {
        int m = m0 + wm + mt * 16 + g;
#pragma unroll
        for (int nt = 0; nt < 8; nt++) {
            int nl = wn + nt * 8 + 2 * t;
            float b0 = sbias[nl], b1 = sbias[nl + 1];
            float2 v0 = { acc[mt][nt][0] + b0, acc[mt][nt][1] + b1 };
            float2 v1 = { acc[mt][nt][2] + b0, acc[mt][nt][3] + b1 };
            *(float2*)&C[(size_t)m * NG + n0 + nl]       = v0;
            *(float2*)&C[(size_t)(m + 8) * NG + n0 + nl] = v1;
        }
    }
}

// ========================= tensor-core persistent GRU scan =========================
// 128 CTAs x 256 thr; CTA = (dir, bhalf:16 batches, jblk:16 j).
// h exchanged as fp16 via g_h16; flag-array release/acquire barrier per 32-CTA group.
#define HS 520            // halfs per h16 row (512 + 8 pad)

__global__ __launch_bounds__(256, 1) void gru_scan(
    const float* __restrict__ giF, const float* __restrict__ giB,
    const float* __restrict__ whhF, const float* __restrict__ whhB,
    const float* __restrict__ bhhF, const float* __restrict__ bhhB,
    const float* __restrict__ h0F,  const float* __restrict__ h0B,
    float* __restrict__ out, float* __restrict__ finF, float* __restrict__ finB)
{
    __shared__ __half h16[16 * HS];          // staged h (fp16)
    __shared__ float sg[3 * 16 * 18];        // gate exchange [gate][b][18]

    int c = blockIdx.x;
    int dir = c >> 6, cid = c & 63, bhalf = cid & 1, jblk = cid >> 1;
    int grp = dir * 2 + bhalf;
    unsigned* flags = g_flag[grp];
    int tid = threadIdx.x, w = tid >> 5, lane = tid & 31;
    int g = lane >> 2, t = lane & 3;

    const float* gi  = dir ? giB  : giF;
    const float* whh = dir ? whhB : whhF;
    const float* bhh = dir ? bhhB : bhhF;
    const float* h0  = dir ? h0B  : h0F;
    float* fin = dir ? finB : finF;

    // ---- thread identity for staging / gate math: (b, jj) ----
    int eb = tid >> 4, ejj = tid & 15;
    int ej  = jblk * 16 + ejj;
    int ebl = bhalf * 16 + eb;
    float bhr = bhh[ej], bhz = bhh[HD + ej], bhn = bhh[2 * HD + ej];
    float hp = __ldcg(&h0[(size_t)ebl * HD + ej]);   // own h carried in fp32 reg

    // ---- preload Whh fragments (fp16 regs): warp w<6 owns n8 tile w ----
    unsigned bw[32][2];
    if (w < 6) {
        int nl = w * 8 + g;
        int gate = nl >> 4, jj = nl & 15;
        const float* Wr = whh + (size_t)(gate * HD + jblk * 16 + jj) * HD;
#pragma unroll
        for (int kk = 0; kk < 32; kk++) {
            int k0 = kk * 16;
            bw[kk][0] = pack2(Wr[k0 + 2 * t],     Wr[k0 + 2 * t + 1]);
            bw[kk][1] = pack2(Wr[k0 + 2 * t + 8], Wr[k0 + 2 * t + 9]);
        }
    }

    uint32_t h16a = (uint32_t)__cvta_generic_to_shared(h16);
    uint32_t lma = h16a + (uint32_t)(((lane & 15) * HS + (lane >> 4) * 8) * 2);
    __half* stg = h16 + eb * HS + ejj * 32;

    // prefetch gi for step 0
    float gir, giz, gin;
    {
        int t0 = dir ? (TT - 1) : 0;
        size_t gb = ((size_t)t0 * BB + ebl) * NG;
        gir = __ldcs(&gi[gb + ej]);
        giz = __ldcs(&gi[gb + HD + ej]);
        gin = __ldcs(&gi[gb + 2 * HD + ej]);
    }

    for (int s = 0; s < TT; s++) {
        int tt = dir ? (TT - 1 - s) : s;

        // ---- stage h (16 b x 512 fp16) into smem ----
        if (s == 0) {
            const float4* src = (const float4*)(h0 + (size_t)ebl * HD + ejj * 32);
            float4 v[8];
#pragma unroll
            for (int i = 0; i < 8; i++) v[i] = __ldcg(src + i);
#pragma unroll
            for (int q = 0; q < 4; q++) {
                uint4 u;
                u.x = pack2(v[2 * q].x,     v[2 * q].y);
                u.y = pack2(v[2 * q].z,     v[2 * q].w);
                u.z = pack2(v[2 * q + 1].x, v[2 * q + 1].y);
                u.w = pack2(v[2 * q + 1].z, v[2 * q + 1].w);
                *(uint4*)(stg + q * 8) = u;
            }
        } else {
            const uint4* src = (const uint4*)(g_h16[dir][s & 1] + (size_t)ebl * HD + ejj * 32);
#pragma unroll
            for (int q = 0; q < 4; q++) *(uint4*)(stg + q * 8) = __ldcg(src + q);
        }
        __syncthreads();

        // ---- recurrent GEMM on tensor cores ----
        if (w < 6) {
            float acc[4] = { 0.f, 0.f, 0.f, 0.f };
#pragma unroll
            for (int kk = 0; kk < 32; kk++) {
                unsigned a0, a1, a2, a3;
                asm volatile("ldmatrix.sync.aligned.m8n8.x4.shared.b16 {%0,%1,%2,%3}, [%4];"
                             : "=r"(a0), "=r"(a1), "=r"(a2), "=r"(a3)
                             : "r"(lma + kk * 32));
                unsigned af[4] = { a0, a1, a2, a3 };
                mma16(acc, af, bw[kk]);
            }
            int nl = w * 8 + 2 * t;
            int gate = nl >> 4, jj2 = nl & 15;
            float* p = &sg[gate * 288 + g * 18 + jj2];
            *(float2*)p            = make_float2(acc[0], acc[1]);
            *(float2*)(p + 8 * 18) = make_float2(acc[2], acc[3]);
        }
        __syncthreads();

        // ---- gate math (1 thread = 1 (b,j)) ----
        float gr = sg[0 * 288 + eb * 18 + ejj];
        float gz = sg[1 * 288 + eb * 18 + ejj];
        float gn = sg[2 * 288 + eb * 18 + ejj];
        float r  = sigm(gir + gr + bhr);
        float z  = sigm(giz + gz + bhz);
        float n  = tanhf(gin + r * (gn + bhn));
        float hn = (1.f - z) * n + z * hp;
        hp = hn;

        // publish h (fp16) FIRST, then signal early
        g_h16[dir][(s + 1) & 1][(size_t)ebl * HD + ej] = __float2half_rn(hn);
        __syncthreads();                         // all h stores of this CTA done
        if (tid == 0)
            asm volatile("st.release.gpu.global.u32 [%0], %1;"
                         :: "l"(&flags[jblk]), "r"((unsigned)(s + 1)) : "memory");

        // off-critical-path work (overlaps peers' polls)
        __stcs(&out[((size_t)tt * BB + ebl) * 1024 + dir * HD + ej], hn);
        if (s == TT - 1) fin[(size_t)ebl * HD + ej] = hn;
        {
            int s2 = (s + 1 < TT) ? (s + 1) : s;
            int t2 = dir ? (TT - 1 - s2) : s2;
            size_t gb = ((size_t)t2 * BB + ebl) * NG;
            gir = __ldcs(&gi[gb + ej]);
            giz = __ldcs(&gi[gb + HD + ej]);
            gin = __ldcs(&gi[gb + 2 * HD + ej]);
        }

        // ---- group barrier: warp 0 polls all 32 flags (one coalesced line) ----
        if (w == 0) {
            unsigned target = (unsigned)(s + 1);
            unsigned v;
            do {
                asm volatile("ld.acquire.gpu.global.u32 %0, [%1];"
                             : "=r"(v) : "l"(&flags[lane]) : "memory");
            } while (!__all_sync(0xffffffffu, v >= target));
        }
        __syncthreads();
    }
}

__global__ void reset_cnt() { if (threadIdx.x < 128) ((unsigned*)g_flag)[threadIdx.x] = 0u; }

// ========================= host launcher =========================
extern "C" void kernel_launch(void* const* d_in, const int* in_sizes, int n_in,
                              void* d_out, int out_size)
{
    (void)in_sizes; (void)n_in; (void)out_size;
    const float* x  = (const float*)d_in[0];
    const float* h0 = (const float*)d_in[1];
    float* out    = (float*)d_out;
    float* finals = out + (size_t)TT * BB * 1024;

    float *gi0, *gi1, *buf0, *buf1;
    cudaGetSymbolAddress((void**)&gi0,  g_gi0);
    cudaGetSymbolAddress((void**)&gi1,  g_gi1);
    cudaGetSymbolAddress((void**)&buf0, g_buf0);
    cudaGetSymbolAddress((void**)&buf1, g_buf1);

    const float* layin[3]   = { x, buf0, buf1 };
    float*       layout_[3] = { buf0, buf1, out };
    int Ks[3] = { 256, 1024, 1024 };

    dim3 ggrid(NG / BN, MM / BM, 2);   // (12, 256, 2)

    for (int L = 0; L < 3; L++) {
        const float* wih  = (const float*)d_in[2 + L * 8 + 0];
        const float* whh  = (const float*)d_in[2 + L * 8 + 1];
        const float* bih  = (const float*)d_in[2 + L * 8 + 2];
        const float* bhh  = (const float*)d_in[2 + L * 8 + 3];
        const float* wihr = (const float*)d_in[2 + L * 8 + 4];
        const float* whhr = (const float*)d_in[2 + L * 8 + 5];
        const float* bihr = (const float*)d_in[2 + L * 8 + 6];
        const float* bhhr = (const float*)d_in[2 + L * 8 + 7];

        gemm_tc<<<ggrid, 256>>>(layin[L], wih, wihr, bih, bihr, gi0, gi1, Ks[L]);
        reset_cnt<<<1, 128>>>();
        gru_scan<<<128, 256>>>(gi0, gi1, whh, whhr, bhh, bhhr,
                               h0 + (size_t)(2 * L) * BB * HD,
                               h0 + (size_t)(2 * L + 1) * BB * HD,
                               layout_[L],
                               finals + (size_t)(2 * L) * BB * HD,
                               finals + (size_t)(2 * L + 1) * BB * HD);
    }
}

// round 10
// speedup vs baseline: 1.6066x; 1.6066x over previous
#include <cuda_runtime.h>
#include <cuda_fp16.h>
#include <cstdint>

#define TT 1024
#define BB 32
#define HD 512
#define NG 1536           // 3*HD
#define MM (TT*BB)        // 32768

typedef unsigned long long ull;

// ---------------- device scratch (no allocations allowed) ----------------
__device__ float g_gi0[(size_t)MM * NG];     // forward gi
__device__ float g_gi1[(size_t)MM * NG];     // backward gi
__device__ float g_buf0[(size_t)MM * 1024];  // layer0 output
__device__ float g_buf1[(size_t)MM * 1024];  // layer1 output
__device__ __half g_h16[2][2][BB * HD];      // ping-pong h per direction (fp16 exchange)
__device__ unsigned g_cnt4[4 * 32];          // 4 independent barrier counters (128B apart)

// ========================= common helpers =========================
__device__ __forceinline__ unsigned pack2(float a, float b) {
    __half2 h = __floats2half2_rn(a, b);
    return *(unsigned*)&h;
}
__device__ __forceinline__ void mma16(float* d, const unsigned* a, const unsigned* b) {
    asm volatile("mma.sync.aligned.m16n8k16.row.col.f32.f16.f16.f32 "
                 "{%0,%1,%2,%3}, {%4,%5,%6,%7}, {%8,%9}, {%0,%1,%2,%3};"
                 : "+f"(d[0]), "+f"(d[1]), "+f"(d[2]), "+f"(d[3])
                 : "r"(a[0]), "r"(a[1]), "r"(a[2]), "r"(a[3]), "r"(b[0]), "r"(b[1]));
}
__device__ __forceinline__ float sigm(float x) { return 1.f / (1.f + __expf(-x)); }

// ========================= fp16 mma.sync projection GEMM =========================
// C[m][n] = sum_k A[m][k]*W[n][k] + bias[n].  Tile 128x128x32, 8 warps (4Mx2N).
#define BM 128
#define BN 128
#define BK 32
#define SSH 40

__global__ __launch_bounds__(256, 2) void gemm_tc(
    const float* __restrict__ A,
    const float* __restrict__ W0, const float* __restrict__ W1,
    const float* __restrict__ bi0, const float* __restrict__ bi1,
    float* __restrict__ C0, float* __restrict__ C1, int K)
{
    __shared__ __half sAB[2][2][128 * SSH];
    __shared__ float sbias[BN];

    int tid = threadIdx.x, warp = tid >> 5, lane = tid & 31;
    int g = lane >> 2, t = lane & 3;
    int wm = (warp & 3) * 32;
    int wn = (warp >> 2) * 64;

    int n0 = blockIdx.x * BN;
    int m0 = blockIdx.y * BM;
    int dz = blockIdx.z;
    const float* W    = dz ? W1  : W0;
    const float* bias = dz ? bi1 : bi0;
    float*       C    = dz ? C1  : C0;

    if (tid < BN) sbias[tid] = bias[n0 + tid];

    int grow = tid >> 1, gcol = (tid & 1) * 16;
    const float* Ag = A + (size_t)(m0 + grow) * K + gcol;
    const float* Wg = W + (size_t)(n0 + grow) * K + gcol;

    float acc[2][8][4];
#pragma unroll
    for (int mt = 0; mt < 2; mt++)
#pragma unroll
        for (int nt = 0; nt < 8; nt++)
#pragma unroll
            for (int e = 0; e < 4; e++) acc[mt][nt][e] = 0.f;

    int kT = K / BK;
    float4 av[4], wv[4];

#pragma unroll
    for (int q = 0; q < 4; q++) { av[q] = *(const float4*)(Ag + q * 4); wv[q] = *(const float4*)(Wg + q * 4); }
    {
        uint4 ua0 = { pack2(av[0].x, av[0].y), pack2(av[0].z, av[0].w), pack2(av[1].x, av[1].y), pack2(av[1].z, av[1].w) };
        uint4 ua1 = { pack2(av[2].x, av[2].y), pack2(av[2].z, av[2].w), pack2(av[3].x, av[3].y), pack2(av[3].z, av[3].w) };
        uint4 uw0 = { pack2(wv[0].x, wv[0].y), pack2(wv[0].z, wv[0].w), pack2(wv[1].x, wv[1].y), pack2(wv[1].z, wv[1].w) };
        uint4 uw1 = { pack2(wv[2].x, wv[2].y), pack2(wv[2].z, wv[2].w), pack2(wv[3].x, wv[3].y), pack2(wv[3].z, wv[3].w) };
        *(uint4*)&sAB[0][0][grow * SSH + gcol]     = ua0;
        *(uint4*)&sAB[0][0][grow * SSH + gcol + 8] = ua1;
        *(uint4*)&sAB[0][1][grow * SSH + gcol]     = uw0;
        *(uint4*)&sAB[0][1][grow * SSH + gcol + 8] = uw1;
    }
    __syncthreads();

    for (int s = 0; s < kT; s++) {
        int bb = s & 1;
        if (s + 1 < kT) {
            int k0 = (s + 1) * BK;
#pragma unroll
            for (int q = 0; q < 4; q++) {
                av[q] = *(const float4*)(Ag + k0 + q * 4);
                wv[q] = *(const float4*)(Wg + k0 + q * 4);
            }
        }
        const __half* a_s = sAB[bb][0];
        const __half* b_s = sAB[bb][1];
#pragma unroll
        for (int kk = 0; kk < 2; kk++) {
            int k0 = kk * 16;
            unsigned afr[2][4], bfr[8][2];
#pragma unroll
            for (int mt = 0; mt < 2; mt++) {
                int base = (wm + mt * 16 + g) * SSH + k0 + 2 * t;
                afr[mt][0] = *(const unsigned*)&a_s[base];
                afr[mt][1] = *(const unsigned*)&a_s[base + 8 * SSH];
                afr[mt][2] = *(const unsigned*)&a_s[base + 8];
                afr[mt][3] = *(const unsigned*)&a_s[base + 8 * SSH + 8];
            }
#pragma unroll
            for (int nt = 0; nt < 8; nt++) {
                int base = (wn + nt * 8 + g) * SSH + k0 + 2 * t;
                bfr[nt][0] = *(const unsigned*)&b_s[base];
                bfr[nt][1] = *(const unsigned*)&b_s[base + 8];
            }
#pragma unroll
            for (int mt = 0; mt < 2; mt++)
#pragma unroll
                for (int nt = 0; nt < 8; nt++)
                    mma16(acc[mt][nt], afr[mt], bfr[nt]);
        }
        if (s + 1 < kT) {
            uint4 ua0 = { pack2(av[0].x, av[0].y), pack2(av[0].z, av[0].w), pack2(av[1].x, av[1].y), pack2(av[1].z, av[1].w) };
            uint4 ua1 = { pack2(av[2].x, av[2].y), pack2(av[2].z, av[2].w), pack2(av[3].x, av[3].y), pack2(av[3].z, av[3].w) };
            uint4 uw0 = { pack2(wv[0].x, wv[0].y), pack2(wv[0].z, wv[0].w), pack2(wv[1].x, wv[1].y), pack2(wv[1].z, wv[1].w) };
            uint4 uw1 = { pack2(wv[2].x, wv[2].y), pack2(wv[2].z, wv[2].w), pack2(wv[3].x, wv[3].y), pack2(wv[3].z, wv[3].w) };
            int nb = bb ^ 1;
            *(uint4*)&sAB[nb][0][grow * SSH + gcol]     = ua0;
            *(uint4*)&sAB[nb][0][grow * SSH + gcol + 8] = ua1;
            *(uint4*)&sAB[nb][1][grow * SSH + gcol]     = uw0;
            *(uint4*)&sAB[nb][1][grow * SSH + gcol + 8] = uw1;
        }
        __syncthreads();
    }

#pragma unroll
    for (int mt = 0; mt < 2; mt++) {
        int m = m0 + wm + mt * 16 + g;
#pragma unroll
        for (int nt = 0; nt < 8; nt++) {
            int nl = wn + nt * 8 + 2 * t;
            float b0 = sbias[nl], b1 = sbias[nl + 1];
            float2 v0 = { acc[mt][nt][0] + b0, acc[mt][nt][1] + b1 };
            float2 v1 = { acc[mt][nt][2] + b0, acc[mt][nt][3] + b1 };
            *(float2*)&C[(size_t)m * NG + n0 + nl]       = v0;
            *(float2*)&C[(size_t)(m + 8) * NG + n0 + nl] = v1;
        }
    }
}

// ========================= tensor-core persistent GRU scan =========================
// 128 CTAs x 256 thr; CTA = (dir, bhalf:16 batches, jblk:16 j).
// h exchanged as fp16 via g_h16. R8-style barrier: tid0 atomicAdd + single-thread spin.
#define HS 520            // halfs per h16 row (512 + 8 pad)

__global__ __launch_bounds__(256, 1) void gru_scan(
    const float* __restrict__ giF, const float* __restrict__ giB,
    const float* __restrict__ whhF, const float* __restrict__ whhB,
    const float* __restrict__ bhhF, const float* __restrict__ bhhB,
    const float* __restrict__ h0F,  const float* __restrict__ h0B,
    float* __restrict__ out, float* __restrict__ finF, float* __restrict__ finB)
{
    __shared__ __half h16[16 * HS];          // staged h (fp16)
    __shared__ float sg[3 * 16 * 18];        // gate exchange [gate][b][18]

    int c = blockIdx.x;
    int dir = c >> 6, cid = c & 63, bhalf = cid & 1, jblk = cid >> 1;
    unsigned* cnt = &g_cnt4[(dir * 2 + bhalf) * 32];
    int tid = threadIdx.x, w = tid >> 5, lane = tid & 31;
    int g = lane >> 2, t = lane & 3;

    const float* gi  = dir ? giB  : giF;
    const float* whh = dir ? whhB : whhF;
    const float* bhh = dir ? bhhB : bhhF;
    const float* h0  = dir ? h0B  : h0F;
    float* fin = dir ? finB : finF;

    // ---- thread identity for staging / gate math: (b, jj) ----
    int eb = tid >> 4, ejj = tid & 15;
    int ej  = jblk * 16 + ejj;
    int ebl = bhalf * 16 + eb;
    float bhr = bhh[ej], bhz = bhh[HD + ej], bhn = bhh[2 * HD + ej];
    float hp = __ldcg(&h0[(size_t)ebl * HD + ej]);   // own h carried in fp32 reg

    // ---- preload Whh fragments (fp16 regs): warp w<6 owns n8 tile w ----
    unsigned bw[32][2];
    if (w < 6) {
        int nl = w * 8 + g;
        int gate = nl >> 4, jj = nl & 15;
        const float* Wr = whh + (size_t)(gate * HD + jblk * 16 + jj) * HD;
#pragma unroll
        for (int kk = 0; kk < 32; kk++) {
            int k0 = kk * 16;
            bw[kk][0] = pack2(Wr[k0 + 2 * t],     Wr[k0 + 2 * t + 1]);
            bw[kk][1] = pack2(Wr[k0 + 2 * t + 8], Wr[k0 + 2 * t + 9]);
        }
    }

    uint32_t h16a = (uint32_t)__cvta_generic_to_shared(h16);
    uint32_t lma = h16a + (uint32_t)(((lane & 15) * HS + (lane >> 4) * 8) * 2);
    __half* stg = h16 + eb * HS + ejj * 32;

    // prefetch gi for step 0
    float gir, giz, gin;
    {
        int t0 = dir ? (TT - 1) : 0;
        size_t gb = ((size_t)t0 * BB + ebl) * NG;
        gir = __ldcg(&gi[gb + ej]);
        giz = __ldcg(&gi[gb + HD + ej]);
        gin = __ldcg(&gi[gb + 2 * HD + ej]);
    }

    for (int s = 0; s < TT; s++) {
        int tt = dir ? (TT - 1 - s) : s;

        // ---- stage h (16 b x 512 fp16) into smem ----
        if (s == 0) {
            const float4* src = (const float4*)(h0 + (size_t)ebl * HD + ejj * 32);
            float4 v[8];
#pragma unroll
            for (int i = 0; i < 8; i++) v[i] = __ldcg(src + i);
#pragma unroll
            for (int q = 0; q < 4; q++) {
                uint4 u;
                u.x = pack2(v[2 * q].x,     v[2 * q].y);
                u.y = pack2(v[2 * q].z,     v[2 * q].w);
                u.z = pack2(v[2 * q + 1].x, v[2 * q + 1].y);
                u.w = pack2(v[2 * q + 1].z, v[2 * q + 1].w);
                *(uint4*)(stg + q * 8) = u;
            }
        } else {
            const uint4* src = (const uint4*)(g_h16[dir][s & 1] + (size_t)ebl * HD + ejj * 32);
#pragma unroll
            for (int q = 0; q < 4; q++) *(uint4*)(stg + q * 8) = __ldcg(src + q);
        }
        __syncthreads();

        // ---- recurrent GEMM on tensor cores ----
        if (w < 6) {
            float acc[4] = { 0.f, 0.f, 0.f, 0.f };
#pragma unroll
            for (int kk = 0; kk < 32; kk++) {
                unsigned a0, a1, a2, a3;
                asm volatile("ldmatrix.sync.aligned.m8n8.x4.shared.b16 {%0,%1,%2,%3}, [%4];"
                             : "=r"(a0), "=r"(a1), "=r"(a2), "=r"(a3)
                             : "r"(lma + kk * 32));
                unsigned af[4] = { a0, a1, a2, a3 };
                mma16(acc, af, bw[kk]);
            }
            int nl = w * 8 + 2 * t;
            int gate = nl >> 4, jj2 = nl & 15;
            float* p = &sg[gate * 288 + g * 18 + jj2];
            *(float2*)p            = make_float2(acc[0], acc[1]);
            *(float2*)(p + 8 * 18) = make_float2(acc[2], acc[3]);
        }
        __syncthreads();

        // ---- gate math (1 thread = 1 (b,j)) ----
        float gr = sg[0 * 288 + eb * 18 + ejj];
        float gz = sg[1 * 288 + eb * 18 + ejj];
        float gn = sg[2 * 288 + eb * 18 + ejj];
        float r  = sigm(gir + gr + bhr);
        float z  = sigm(giz + gz + bhz);
        float n  = tanhf(gin + r * (gn + bhn));
        float hn = (1.f - z) * n + z * hp;
        hp = hn;

        // publish h (fp16) — the ONLY store the fence must drain
        g_h16[dir][(s + 1) & 1][(size_t)ebl * HD + ej] = __float2half_rn(hn);

        // prefetch next gi (in flight across the barrier)
        {
            int s2 = (s + 1 < TT) ? (s + 1) : s;
            int t2 = dir ? (TT - 1 - s2) : s2;
            size_t gb = ((size_t)t2 * BB + ebl) * NG;
            gir = __ldcg(&gi[gb + ej]);
            giz = __ldcg(&gi[gb + HD + ej]);
            gin = __ldcg(&gi[gb + 2 * HD + ej]);
        }

        // ---- 32-CTA group barrier (R8-proven: atomic + single-thread spin) ----
        __syncthreads();
        if (tid == 0) {
            __threadfence();
            atomicAdd(cnt, 1u);
            unsigned target = (unsigned)(s + 1) * 32u;
            unsigned v;
            do {
                asm volatile("ld.acquire.gpu.u32 %0, [%1];" : "=r"(v) : "l"(cnt) : "memory");
            } while (v < target);
        }
        __syncthreads();

        // ---- off-critical-path output stores (after the signal) ----
        out[((size_t)tt * BB + ebl) * 1024 + dir * HD + ej] = hn;
        if (s == TT - 1) fin[(size_t)ebl * HD + ej] = hn;
    }
}

__global__ void reset_cnt() { if (threadIdx.x < 128) g_cnt4[threadIdx.x] = 0u; }

// ========================= host launcher =========================
extern "C" void kernel_launch(void* const* d_in, const int* in_sizes, int n_in,
                              void* d_out, int out_size)
{
    (void)in_sizes; (void)n_in; (void)out_size;
    const float* x  = (const float*)d_in[0];
    const float* h0 = (const float*)d_in[1];
    float* out    = (float*)d_out;
    float* finals = out + (size_t)TT * BB * 1024;

    float *gi0, *gi1, *buf0, *buf1;
    cudaGetSymbolAddress((void**)&gi0,  g_gi0);
    cudaGetSymbolAddress((void**)&gi1,  g_gi1);
    cudaGetSymbolAddress((void**)&buf0, g_buf0);
    cudaGetSymbolAddress((void**)&buf1, g_buf1);

    const float* layin[3]   = { x, buf0, buf1 };
    float*       layout_[3] = { buf0, buf1, out };
    int Ks[3] = { 256, 1024, 1024 };

    dim3 ggrid(NG / BN, MM / BM, 2);   // (12, 256, 2)

    for (int L = 0; L < 3; L++) {
        const float* wih  = (const float*)d_in[2 + L * 8 + 0];
        const float* whh  = (const float*)d_in[2 + L * 8 + 1];
        const float* bih  = (const float*)d_in[2 + L * 8 + 2];
        const float* bhh  = (const float*)d_in[2 + L * 8 + 3];
        const float* wihr = (const float*)d_in[2 + L * 8 + 4];
        const float* whhr = (const float*)d_in[2 + L * 8 + 5];
        const float* bihr = (const float*)d_in[2 + L * 8 + 6];
        const float* bhhr = (const float*)d_in[2 + L * 8 + 7];

        gemm_tc<<<ggrid, 256>>>(layin[L], wih, wihr, bih, bihr, gi0, gi1, Ks[L]);
        reset_cnt<<<1, 128>>>();
        gru_scan<<<128, 256>>>(gi0, gi1, whh, whhr, bhh, bhhr,
                               h0 + (size_t)(2 * L) * BB * HD,
                               h0 + (size_t)(2 * L + 1) * BB * HD,
                               layout_[L],
                               finals + (size_t)(2 * L) * BB * HD,
                               finals + (size_t)(2 * L + 1) * BB * HD);
    }
}